// round 10
// baseline (speedup 1.0000x reference)
#include <cuda_runtime.h>
#include <cuda_bf16.h>
#include <cstdint>
#include <cstddef>

#define B_  2
#define S_  2048
#define D_  1024
#define H_  16
#define HD_ 64
#define LOG2E 1.4426950408889634f
#define SW128(o) ((o) ^ (((o) >> 3) & 0x70))

// ---------------- static device scratch (allocation-free rule) ----------------
__device__ __nv_bfloat16 g_enc_h[(size_t)4096 * 1024];
__device__ __nv_bfloat16 g_enc_l[(size_t)4096 * 1024];
__device__ __nv_bfloat16 g_w_h[(size_t)2048 * 1024];
__device__ __nv_bfloat16 g_w_l[(size_t)2048 * 1024];
__device__ __nv_bfloat16 g_qh[(size_t)B_ * H_ * S_ * HD_];
__device__ __nv_bfloat16 g_ql[(size_t)B_ * H_ * S_ * HD_];
__device__ __nv_bfloat16 g_kh[(size_t)B_ * H_ * S_ * HD_];
__device__ __nv_bfloat16 g_kl[(size_t)B_ * H_ * S_ * HD_];

// ---------------- helpers (family-common ISA only: sm_80+) ----------------
__device__ __forceinline__ uint32_t smem_addr(const void* p) {
    uint32_t a;
    asm("{ .reg .u64 t; cvta.to.shared.u64 t, %1; cvt.u32.u64 %0, t; }" : "=r"(a) : "l"(p));
    return a;
}
#define CP_ASYNC16(dst, src) \
    asm volatile("cp.async.cg.shared.global [%0], [%1], 16;" :: "r"(dst), "l"(src))
#define CP_COMMIT() asm volatile("cp.async.commit_group;" ::: "memory")
#define CP_WAIT0()  asm volatile("cp.async.wait_group 0;" ::: "memory")

#define LDSM4(r, a)                                                            \
    asm volatile("ldmatrix.sync.aligned.m8n8.x4.shared.b16 {%0,%1,%2,%3}, [%4];" \
        : "=r"((r)[0]), "=r"((r)[1]), "=r"((r)[2]), "=r"((r)[3]) : "r"(a))

__device__ __forceinline__ void mma_bf16(float* c, const uint32_t* a, const uint32_t* b) {
    asm volatile(
        "mma.sync.aligned.m16n8k16.row.col.f32.bf16.bf16.f32 "
        "{%0,%1,%2,%3}, {%4,%5,%6,%7}, {%8,%9}, {%0,%1,%2,%3};"
        : "+f"(c[0]), "+f"(c[1]), "+f"(c[2]), "+f"(c[3])
        : "r"(a[0]), "r"(a[1]), "r"(a[2]), "r"(a[3]), "r"(b[0]), "r"(b[1]));
}

__device__ __forceinline__ float ex2(float x) {       // MUFU path (phase B)
    float y;
    asm("ex2.approx.ftz.f32 %0, %1;" : "=f"(y) : "f"(x));
    return y;
}

// FMA-pipe exp2: round via magic constant + degree-5 Taylor on f in [-.5,.5].
// Max rel err ~2.4e-6. Keeps MUFU free for other warps' phase-B ex2.
__device__ __forceinline__ float exp2_poly(float x) {
    const float MAGIC = 12582912.f;                   // 1.5 * 2^23
    float t = x + MAGIC;
    int   n = __float_as_int(t) - 0x4B400000;         // round(x)
    float f = x - (t - MAGIC);                        // [-0.5, 0.5]
    float p = 0.00133336f;
    p = fmaf(p, f, 0.00961813f);
    p = fmaf(p, f, 0.05550411f);
    p = fmaf(p, f, 0.24022651f);
    p = fmaf(p, f, 0.69314718f);
    p = fmaf(p, f, 1.0f);
    return p * __int_as_float((n + 127) << 23);
}

__device__ __forceinline__ void split2(float a, float b, __nv_bfloat162& h, __nv_bfloat162& l) {
    __nv_bfloat16 ha = __float2bfloat16_rn(a), hb = __float2bfloat16_rn(b);
    h.x = ha; h.y = hb;
    l.x = __float2bfloat16_rn(a - __bfloat162float(ha));
    l.y = __float2bfloat16_rn(b - __bfloat162float(hb));
}

// ---------------- split kernel: fp32 -> bf16 hi/lo (enc + W in one launch) ----------------
__global__ void split_all(const float* __restrict__ enc, const float* __restrict__ Wm) {
    const int bx = blockIdx.x;
    if (bx < 4096) {
        int i = bx * 256 + threadIdx.x;
        float4 v = ((const float4*)enc)[i];
        __nv_bfloat162 h01, l01, h23, l23;
        split2(v.x, v.y, h01, l01);
        split2(v.z, v.w, h23, l23);
        ((__nv_bfloat162*)g_enc_h)[2 * i]     = h01;
        ((__nv_bfloat162*)g_enc_h)[2 * i + 1] = h23;
        ((__nv_bfloat162*)g_enc_l)[2 * i]     = l01;
        ((__nv_bfloat162*)g_enc_l)[2 * i + 1] = l23;
    } else {
        int i = (bx - 4096) * 256 + threadIdx.x;
        float4 v = ((const float4*)Wm)[i];
        __nv_bfloat162 h01, l01, h23, l23;
        split2(v.x, v.y, h01, l01);
        split2(v.z, v.w, h23, l23);
        ((__nv_bfloat162*)g_w_h)[2 * i]     = h01;
        ((__nv_bfloat162*)g_w_h)[2 * i + 1] = h23;
        ((__nv_bfloat162*)g_w_l)[2 * i]     = l01;
        ((__nv_bfloat162*)g_w_l)[2 * i + 1] = l23;
    }
}

// ---------------- projection GEMM (+ overlapped output zero-fill blocks) ----------------
// blockIdx.x <  32 : GEMM block tile 128(M) x 64(N), 4 warps x (32x64), K-chunk 64.
// blockIdx.x >= 32 : zero-fill of out's causal upper triangle (pure stores,
//                    overlaps with GEMM tensor work; region disjoint from attn writes).
// smem buf (48KB): Ah@0 Al@16384 Bh@32768 Bl@40960 ; x2 buffers = 96KB -> 2 blocks/SM
#define PROJ_BUF 49152
#define PROJ_SMEM (2 * PROJ_BUF)

__global__ __launch_bounds__(128, 2) void proj_mma(const float* __restrict__ bias,
                                                   float* __restrict__ out) {
    if (blockIdx.x >= 32) {                         // ---- zero-fill path ----
        const int bx = blockIdx.x - 32;             // 0..15 row-tile
        const int bh = blockIdx.y;                  // 0..31
        const int cbase = bx * 128 + 128;
        const int len = S_ - cbase;
        if (len > 0) {
            float4* p = (float4*)(out + ((size_t)bh * S_ + bx * 128 + threadIdx.x) * S_ + cbase);
            const int n4 = len >> 2;
            const float4 z = make_float4(0.f, 0.f, 0.f, 0.f);
            for (int i = 0; i < n4; i++) __stcs(p + i, z);
        }
        return;
    }

    extern __shared__ char smem[];
    const int tid = threadIdx.x, l = tid & 31, w = tid >> 5;
    const int e0 = blockIdx.x * 64, m0 = blockIdx.y * 128;
    const uint32_t sb = smem_addr(smem);

    auto prefetch = [&](int buf, int k0) {
        #pragma unroll
        for (int i = 0; i < 24; i++) {
            int gi = tid + i * 128;                 // 0..3071
            const __nv_bfloat16* src;
            uint32_t dst;
            if (gi < 2048) {                        // A: 128 rows x 8 c8 x (h,l)
                int tl = gi >> 10, idx = gi & 1023, row = idx >> 3, c8 = idx & 7;
                src = (tl ? g_enc_l : g_enc_h) + (size_t)(m0 + row) * D_ + k0 + c8 * 8;
                dst = sb + buf * PROJ_BUF + tl * 16384 + SW128(row * 128 + c8 * 16);
            } else {                                // B: 64 rows x 8 c8 x (h,l)
                int gj = gi - 2048;
                int tl = gj >> 9, idx = gj & 511, row = idx >> 3, c8 = idx & 7;
                src = (tl ? g_w_l : g_w_h) + (size_t)(e0 + row) * D_ + k0 + c8 * 8;
                dst = sb + buf * PROJ_BUF + 32768 + tl * 8192 + SW128(row * 128 + c8 * 16);
            }
            CP_ASYNC16(dst, src);
        }
    };

    prefetch(0, 0);
    CP_COMMIT();

    float acc[2][8][4];
    #pragma unroll
    for (int mt = 0; mt < 2; mt++)
        #pragma unroll
        for (int nt = 0; nt < 8; nt++)
            #pragma unroll
            for (int e = 0; e < 4; e++) acc[mt][nt][e] = 0.f;

    for (int j = 0; j < 16; j++) {
        CP_WAIT0();
        __syncthreads();
        if (j < 15) { prefetch((j + 1) & 1, (j + 1) * 64); CP_COMMIT(); }

        const uint32_t tb = sb + (j & 1) * PROJ_BUF;
        #pragma unroll
        for (int s = 0; s < 4; s++) {
            const int acol = s * 32 + ((l >> 4) << 4);
            uint32_t ah[2][4], al[2][4];
            #pragma unroll
            for (int mt = 0; mt < 2; mt++) {
                const int arow = 32 * w + mt * 16 + (l & 15);
                LDSM4(ah[mt], tb + SW128(arow * 128 + acol));
                LDSM4(al[mt], tb + 16384 + SW128(arow * 128 + acol));
            }
            #pragma unroll
            for (int tp = 0; tp < 4; tp++) {
                const int brow = tp * 16 + (l & 7) + ((l >> 4) << 3);
                const int bcol = s * 32 + (((l >> 3) & 1) << 4);
                uint32_t bhf[4], blf[4];
                LDSM4(bhf, tb + 32768 + SW128(brow * 128 + bcol));
                LDSM4(blf, tb + 40960 + SW128(brow * 128 + bcol));
                #pragma unroll
                for (int mt = 0; mt < 2; mt++)
                    #pragma unroll
                    for (int nn = 0; nn < 2; nn++) {
                        float* c = acc[mt][2 * tp + nn];
                        mma_bf16(c, ah[mt], bhf + 2 * nn);
                        mma_bf16(c, ah[mt], blf + 2 * nn);
                        mma_bf16(c, al[mt], bhf + 2 * nn);
                    }
            }
        }
        __syncthreads();
    }

    // Epilogue: bias; q gets 0.125*log2(e) folded in (scores land in log2 domain).
    const bool isq = (e0 < D_);
    const int eh = isq ? e0 : e0 - D_;
    const int head = eh >> 6;
    const float scf = isq ? (0.125f * LOG2E) : 1.0f;
    __nv_bfloat16* dhb = isq ? g_qh : g_kh;
    __nv_bfloat16* dlb = isq ? g_ql : g_kl;

    #pragma unroll
    for (int mt = 0; mt < 2; mt++)
        #pragma unroll
        for (int nt = 0; nt < 8; nt++) {
            const int cp = e0 + nt * 8 + 2 * (l & 3);
            const int hd0 = cp & 63;
            const float b0 = __ldg(bias + cp), b1 = __ldg(bias + cp + 1);
            #pragma unroll
            for (int rh = 0; rh < 2; rh++) {
                const int m = m0 + 32 * w + mt * 16 + (l >> 2) + rh * 8;
                const int bb = m >> 11, s = m & (S_ - 1);
                const size_t base = (((size_t)bb * H_ + head) * S_ + s) * HD_ + hd0;
                const float v0 = (acc[mt][nt][2 * rh]     + b0) * scf;
                const float v1 = (acc[mt][nt][2 * rh + 1] + b1) * scf;
                __nv_bfloat162 h2, l2;
                split2(v0, v1, h2, l2);
                *(__nv_bfloat162*)(dhb + base) = h2;
                *(__nv_bfloat162*)(dlb + base) = l2;
            }
        }
}

// ---------------- fused attention: 4 warps x 32 q-rows, 64-row K chunks ----------------
// smem: Q hi@0 lo@16384 ; K buf b at 32768 + b*16384 (hi@0 lo@8192 within buf)
// 64KB/block -> 3 blocks/SM; acc 64 regs -> no spills.
#define ATTN_SMEM (32768 + 2 * 16384)

__device__ __forceinline__ void mma_chunk64(float (&acc)[2][8][4], uint32_t qb, uint32_t kb,
                                            int l, int w) {
    #pragma unroll
    for (int mt = 0; mt < 2; mt++)
        #pragma unroll
        for (int nt = 0; nt < 8; nt++)
            #pragma unroll
            for (int e = 0; e < 4; e++) acc[mt][nt][e] = 0.f;

    #pragma unroll
    for (int s = 0; s < 4; s++) {
        const int acol = s * 32 + ((l >> 4) << 4);
        uint32_t ah[2][4], al[2][4];
        #pragma unroll
        for (int mt = 0; mt < 2; mt++) {
            const int arow = 32 * w + mt * 16 + (l & 15);
            LDSM4(ah[mt], qb + SW128(arow * 128 + acol));
            LDSM4(al[mt], qb + 16384 + SW128(arow * 128 + acol));
        }
        #pragma unroll
        for (int tp = 0; tp < 4; tp++) {
            const int brow = tp * 16 + (l & 7) + ((l >> 4) << 3);
            const int bcol = s * 32 + (((l >> 3) & 1) << 4);
            uint32_t bhf[4], blf[4];
            LDSM4(bhf, kb + SW128(brow * 128 + bcol));
            LDSM4(blf, kb + 8192 + SW128(brow * 128 + bcol));
            #pragma unroll
            for (int mt = 0; mt < 2; mt++)
                #pragma unroll
                for (int nn = 0; nn < 2; nn++) {
                    float* c = acc[mt][2 * tp + nn];
                    mma_bf16(c, ah[mt], bhf + 2 * nn);
                    mma_bf16(c, ah[mt], blf + 2 * nn);
                    mma_bf16(c, al[mt], bhf + 2 * nn);
                }
        }
    }
}

__global__ __launch_bounds__(128, 3) void attn_fused(float* __restrict__ out) {
    extern __shared__ char smem[];
    const int tid = threadIdx.x, l = tid & 31, w = tid >> 5;
    const int bx = 15 - blockIdx.x;                // big tiles launch first
    const int t0 = bx * 128;
    const int bh = blockIdx.z * H_ + blockIdx.y;
    const uint32_t sb = smem_addr(smem);

    const __nv_bfloat16* qh = g_qh + ((size_t)bh * S_ + t0) * HD_;
    const __nv_bfloat16* ql = g_ql + ((size_t)bh * S_ + t0) * HD_;
    const __nv_bfloat16* khb = g_kh + (size_t)bh * S_ * HD_;
    const __nv_bfloat16* klb = g_kl + (size_t)bh * S_ * HD_;

    auto prefetch_k = [&](int buf, int chunk) {      // 64-row chunk: 16KB
        const __nv_bfloat16* kh = khb + (size_t)chunk * 64 * HD_;
        const __nv_bfloat16* kl = klb + (size_t)chunk * 64 * HD_;
        #pragma unroll
        for (int i = 0; i < 8; i++) {
            int gi = tid + i * 128;
            int tl = gi >> 9, idx = gi & 511, row = idx >> 3, c8 = idx & 7;
            CP_ASYNC16(sb + 32768 + buf * 16384 + tl * 8192 + SW128(row * 128 + c8 * 16),
                       (tl ? kl : kh) + row * HD_ + c8 * 8);
        }
    };

    // Q (persistent, 32KB) + K chunk 0
    #pragma unroll
    for (int i = 0; i < 16; i++) {
        int gi = tid + i * 128;
        int tl = gi >> 10, idx = gi & 1023, row = idx >> 3, c8 = idx & 7;
        CP_ASYNC16(sb + tl * 16384 + SW128(row * 128 + c8 * 16),
                   (tl ? ql : qh) + row * HD_ + c8 * 8);
    }
    prefetch_k(0, 0);
    CP_COMMIT();

    const int rq = (l >> 2);                       // quad row within 8
    const int nj = 2 * bx + 2;                     // causal 64-col chunks
    float d[2][2] = {{0.f, 0.f}, {0.f, 0.f}};      // [mt][rowhalf] sums of 2^score

    // ---- phase A: row sums (exp2 on FMA pipe; MUFU left for phase-B warps) ----
    for (int j = 0; j < nj; j++) {
        CP_WAIT0();
        __syncthreads();
        prefetch_k((j + 1) & 1, (j + 1 < nj) ? j + 1 : 0);   // wraps to phase-B chunk 0
        CP_COMMIT();

        const uint32_t kb = sb + 32768 + (j & 1) * 16384;
        float acc[2][8][4];
        mma_chunk64(acc, sb, kb, l, w);

        const bool diag = (j >= 2 * bx);
        const int coff = (j - 2 * bx) * 64;
        #pragma unroll
        for (int mt = 0; mt < 2; mt++) {
            const int rr0 = 32 * w + 16 * mt + rq, rr1 = rr0 + 8;
            #pragma unroll
            for (int nt = 0; nt < 8; nt++)
                #pragma unroll
                for (int e = 0; e < 2; e++) {
                    const int cl = nt * 8 + 2 * (l & 3) + e;
                    float e0 = exp2_poly(acc[mt][nt][e]);
                    float e1 = exp2_poly(acc[mt][nt][2 + e]);
                    if (diag) {
                        if (coff + cl > rr0) e0 = 0.f;
                        if (coff + cl > rr1) e1 = 0.f;
                    }
                    d[mt][0] += e0; d[mt][1] += e1;
                }
        }
    }

    // full row sum lives in the 4 lanes of each quad
    #pragma unroll
    for (int off = 1; off <= 2; off <<= 1) {
        #pragma unroll
        for (int mt = 0; mt < 2; mt++) {
            d[mt][0] += __shfl_xor_sync(0xffffffffu, d[mt][0], off);
            d[mt][1] += __shfl_xor_sync(0xffffffffu, d[mt][1], off);
        }
    }
    float vi[2][2];
    #pragma unroll
    for (int mt = 0; mt < 2; mt++) {
        vi[mt][0] = 1.f / d[mt][0];
        vi[mt][1] = 1.f / d[mt][1];
    }

    // ---- phase B: probabilities ----
    for (int j = 0; j < nj; j++) {
        CP_WAIT0();
        __syncthreads();
        if (j + 1 < nj) { prefetch_k((nj + j + 1) & 1, j + 1); CP_COMMIT(); }

        const uint32_t kb = sb + 32768 + ((nj + j) & 1) * 16384;
        float acc[2][8][4];
        mma_chunk64(acc, sb, kb, l, w);

        const bool diag = (j >= 2 * bx);
        const int coff = (j - 2 * bx) * 64;
        #pragma unroll
        for (int mt = 0; mt < 2; mt++) {
            const int rr0 = 32 * w + 16 * mt + rq, rr1 = rr0 + 8;
            float* o0 = out + ((size_t)bh * S_ + t0 + rr0) * S_ + j * 64 + 2 * (l & 3);
            float* o1 = out + ((size_t)bh * S_ + t0 + rr1) * S_ + j * 64 + 2 * (l & 3);
            #pragma unroll
            for (int nt = 0; nt < 8; nt++) {
                const int cl = nt * 8 + 2 * (l & 3);
                float2 p0, p1;
                p0.x = ex2(acc[mt][nt][0]) * vi[mt][0];
                p0.y = ex2(acc[mt][nt][1]) * vi[mt][0];
                p1.x = ex2(acc[mt][nt][2]) * vi[mt][1];
                p1.y = ex2(acc[mt][nt][3]) * vi[mt][1];
                if (diag) {
                    if (coff + cl     > rr0) p0.x = 0.f;
                    if (coff + cl + 1 > rr0) p0.y = 0.f;
                    if (coff + cl     > rr1) p1.x = 0.f;
                    if (coff + cl + 1 > rr1) p1.y = 0.f;
                }
                __stcs((float2*)(o0 + nt * 8), p0);
                __stcs((float2*)(o1 + nt * 8), p1);
            }
        }
    }
    // (zero-fill of future columns now happens in proj_mma's extra blocks)
}

// ---------------------------------------------------------------------------
extern "C" void kernel_launch(void* const* d_in, const int* in_sizes, int n_in,
                              void* d_out, int out_size)
{
    (void)in_sizes; (void)n_in; (void)out_size;
    const float* encoded = (const float*)d_in[0];  // [2, 2048, 1024]
    const float* W       = (const float*)d_in[1];  // [2048, 1024]
    const float* bias    = (const float*)d_in[2];  // [2048]
    float* out = (float*)d_out;                    // [2, 16, 2048, 2048]

    cudaFuncSetAttribute(proj_mma,   cudaFuncAttributeMaxDynamicSharedMemorySize, PROJ_SMEM);
    cudaFuncSetAttribute(attn_fused, cudaFuncAttributeMaxDynamicSharedMemorySize, ATTN_SMEM);

    split_all<<<6144, 256>>>(encoded, W);
    proj_mma<<<dim3(48, 32), 128, PROJ_SMEM>>>(bias, out);
    attn_fused<<<dim3(16, H_, B_), 128, ATTN_SMEM>>>(out);
}

// round 11
// speedup vs baseline: 1.1417x; 1.1417x over previous
#include <cuda_runtime.h>
#include <cuda_bf16.h>
#include <cstdint>
#include <cstddef>

#define B_  2
#define S_  2048
#define D_  1024
#define H_  16
#define HD_ 64
#define LOG2E 1.4426950408889634f
#define SW128(o) ((o) ^ (((o) >> 3) & 0x70))

// ---------------- static device scratch (allocation-free rule) ----------------
__device__ __nv_bfloat16 g_enc_h[(size_t)4096 * 1024];
__device__ __nv_bfloat16 g_enc_l[(size_t)4096 * 1024];
__device__ __nv_bfloat16 g_w_h[(size_t)2048 * 1024];
__device__ __nv_bfloat16 g_w_l[(size_t)2048 * 1024];
__device__ __nv_bfloat16 g_qh[(size_t)B_ * H_ * S_ * HD_];
__device__ __nv_bfloat16 g_ql[(size_t)B_ * H_ * S_ * HD_];
__device__ __nv_bfloat16 g_kh[(size_t)B_ * H_ * S_ * HD_];
__device__ __nv_bfloat16 g_kl[(size_t)B_ * H_ * S_ * HD_];

// ---------------- helpers (family-common ISA only: sm_80+) ----------------
__device__ __forceinline__ uint32_t smem_addr(const void* p) {
    uint32_t a;
    asm("{ .reg .u64 t; cvta.to.shared.u64 t, %1; cvt.u32.u64 %0, t; }" : "=r"(a) : "l"(p));
    return a;
}
#define CP_ASYNC16(dst, src) \
    asm volatile("cp.async.cg.shared.global [%0], [%1], 16;" :: "r"(dst), "l"(src))
#define CP_COMMIT() asm volatile("cp.async.commit_group;" ::: "memory")
#define CP_WAIT0()  asm volatile("cp.async.wait_group 0;" ::: "memory")

#define LDSM4(r, a)                                                            \
    asm volatile("ldmatrix.sync.aligned.m8n8.x4.shared.b16 {%0,%1,%2,%3}, [%4];" \
        : "=r"((r)[0]), "=r"((r)[1]), "=r"((r)[2]), "=r"((r)[3]) : "r"(a))

__device__ __forceinline__ void mma_bf16(float* c, const uint32_t* a, const uint32_t* b) {
    asm volatile(
        "mma.sync.aligned.m16n8k16.row.col.f32.bf16.bf16.f32 "
        "{%0,%1,%2,%3}, {%4,%5,%6,%7}, {%8,%9}, {%0,%1,%2,%3};"
        : "+f"(c[0]), "+f"(c[1]), "+f"(c[2]), "+f"(c[3])
        : "r"(a[0]), "r"(a[1]), "r"(a[2]), "r"(a[3]), "r"(b[0]), "r"(b[1]));
}

__device__ __forceinline__ float ex2(float x) {
    float y;
    asm("ex2.approx.ftz.f32 %0, %1;" : "=f"(y) : "f"(x));
    return y;
}

__device__ __forceinline__ void split2(float a, float b, __nv_bfloat162& h, __nv_bfloat162& l) {
    __nv_bfloat16 ha = __float2bfloat16_rn(a), hb = __float2bfloat16_rn(b);
    h.x = ha; h.y = hb;
    l.x = __float2bfloat16_rn(a - __bfloat162float(ha));
    l.y = __float2bfloat16_rn(b - __bfloat162float(hb));
}

// ---------------- split kernel: fp32 -> bf16 hi/lo (enc + W in one launch) ----------------
__global__ void split_all(const float* __restrict__ enc, const float* __restrict__ Wm) {
    const int bx = blockIdx.x;
    if (bx < 4096) {
        int i = bx * 256 + threadIdx.x;
        float4 v = ((const float4*)enc)[i];
        __nv_bfloat162 h01, l01, h23, l23;
        split2(v.x, v.y, h01, l01);
        split2(v.z, v.w, h23, l23);
        ((__nv_bfloat162*)g_enc_h)[2 * i]     = h01;
        ((__nv_bfloat162*)g_enc_h)[2 * i + 1] = h23;
        ((__nv_bfloat162*)g_enc_l)[2 * i]     = l01;
        ((__nv_bfloat162*)g_enc_l)[2 * i + 1] = l23;
    } else {
        int i = (bx - 4096) * 256 + threadIdx.x;
        float4 v = ((const float4*)Wm)[i];
        __nv_bfloat162 h01, l01, h23, l23;
        split2(v.x, v.y, h01, l01);
        split2(v.z, v.w, h23, l23);
        ((__nv_bfloat162*)g_w_h)[2 * i]     = h01;
        ((__nv_bfloat162*)g_w_h)[2 * i + 1] = h23;
        ((__nv_bfloat162*)g_w_l)[2 * i]     = l01;
        ((__nv_bfloat162*)g_w_l)[2 * i + 1] = l23;
    }
}

// ---------------- projection GEMM: qk = enc @ W^T + bias ----------------
// Block tile 128(M) x 64(N=one head's dims), 4 warps x (32x64), K-chunk 64.
// smem buf (48KB): Ah@0 Al@16384 Bh@32768 Bl@40960 ; x2 buffers = 96KB -> 2 blocks/SM
#define PROJ_BUF 49152
#define PROJ_SMEM (2 * PROJ_BUF)

__global__ __launch_bounds__(128, 2) void proj_mma(const float* __restrict__ bias) {
    extern __shared__ char smem[];
    const int tid = threadIdx.x, l = tid & 31, w = tid >> 5;
    const int e0 = blockIdx.x * 64, m0 = blockIdx.y * 128;
    const uint32_t sb = smem_addr(smem);

    auto prefetch = [&](int buf, int k0) {
        #pragma unroll
        for (int i = 0; i < 24; i++) {
            int gi = tid + i * 128;                 // 0..3071
            const __nv_bfloat16* src;
            uint32_t dst;
            if (gi < 2048) {                        // A: 128 rows x 8 c8 x (h,l)
                int tl = gi >> 10, idx = gi & 1023, row = idx >> 3, c8 = idx & 7;
                src = (tl ? g_enc_l : g_enc_h) + (size_t)(m0 + row) * D_ + k0 + c8 * 8;
                dst = sb + buf * PROJ_BUF + tl * 16384 + SW128(row * 128 + c8 * 16);
            } else {                                // B: 64 rows x 8 c8 x (h,l)
                int gj = gi - 2048;
                int tl = gj >> 9, idx = gj & 511, row = idx >> 3, c8 = idx & 7;
                src = (tl ? g_w_l : g_w_h) + (size_t)(e0 + row) * D_ + k0 + c8 * 8;
                dst = sb + buf * PROJ_BUF + 32768 + tl * 8192 + SW128(row * 128 + c8 * 16);
            }
            CP_ASYNC16(dst, src);
        }
    };

    prefetch(0, 0);
    CP_COMMIT();

    float acc[2][8][4];
    #pragma unroll
    for (int mt = 0; mt < 2; mt++)
        #pragma unroll
        for (int nt = 0; nt < 8; nt++)
            #pragma unroll
            for (int e = 0; e < 4; e++) acc[mt][nt][e] = 0.f;

    for (int j = 0; j < 16; j++) {
        CP_WAIT0();
        __syncthreads();
        if (j < 15) { prefetch((j + 1) & 1, (j + 1) * 64); CP_COMMIT(); }

        const uint32_t tb = sb + (j & 1) * PROJ_BUF;
        #pragma unroll
        for (int s = 0; s < 4; s++) {
            const int acol = s * 32 + ((l >> 4) << 4);
            uint32_t ah[2][4], al[2][4];
            #pragma unroll
            for (int mt = 0; mt < 2; mt++) {
                const int arow = 32 * w + mt * 16 + (l & 15);
                LDSM4(ah[mt], tb + SW128(arow * 128 + acol));
                LDSM4(al[mt], tb + 16384 + SW128(arow * 128 + acol));
            }
            #pragma unroll
            for (int tp = 0; tp < 4; tp++) {
                const int brow = tp * 16 + (l & 7) + ((l >> 4) << 3);
                const int bcol = s * 32 + (((l >> 3) & 1) << 4);
                uint32_t bhf[4], blf[4];
                LDSM4(bhf, tb + 32768 + SW128(brow * 128 + bcol));
                LDSM4(blf, tb + 40960 + SW128(brow * 128 + bcol));
                #pragma unroll
                for (int mt = 0; mt < 2; mt++)
                    #pragma unroll
                    for (int nn = 0; nn < 2; nn++) {
                        float* c = acc[mt][2 * tp + nn];
                        mma_bf16(c, ah[mt], bhf + 2 * nn);
                        mma_bf16(c, ah[mt], blf + 2 * nn);
                        mma_bf16(c, al[mt], bhf + 2 * nn);
                    }
            }
        }
        __syncthreads();
    }

    // Epilogue: bias; q gets 0.125*log2(e) folded in (scores land in log2 domain).
    const bool isq = (e0 < D_);
    const int eh = isq ? e0 : e0 - D_;
    const int head = eh >> 6;
    const float scf = isq ? (0.125f * LOG2E) : 1.0f;
    __nv_bfloat16* dhb = isq ? g_qh : g_kh;
    __nv_bfloat16* dlb = isq ? g_ql : g_kl;

    #pragma unroll
    for (int mt = 0; mt < 2; mt++)
        #pragma unroll
        for (int nt = 0; nt < 8; nt++) {
            const int cp = e0 + nt * 8 + 2 * (l & 3);
            const int hd0 = cp & 63;
            const float b0 = __ldg(bias + cp), b1 = __ldg(bias + cp + 1);
            #pragma unroll
            for (int rh = 0; rh < 2; rh++) {
                const int m = m0 + 32 * w + mt * 16 + (l >> 2) + rh * 8;
                const int bb = m >> 11, s = m & (S_ - 1);
                const size_t base = (((size_t)bb * H_ + head) * S_ + s) * HD_ + hd0;
                const float v0 = (acc[mt][nt][2 * rh]     + b0) * scf;
                const float v1 = (acc[mt][nt][2 * rh + 1] + b1) * scf;
                __nv_bfloat162 h2, l2;
                split2(v0, v1, h2, l2);
                *(__nv_bfloat162*)(dhb + base) = h2;
                *(__nv_bfloat162*)(dlb + base) = l2;
            }
        }
}

// ---------------- fused attention: 4 warps x 32 q-rows, 64-row K chunks ----------------
// smem: Q hi@0 lo@16384 ; K buf b at 32768 + b*16384 (hi@0 lo@8192 within buf)
// 64KB/block -> 3 blocks/SM; acc 64 regs -> no spills.
// Zero-fill of the causal upper triangle is interleaved into the MMA loop
// iterations (store pipe idle during tensor work) instead of a serial tail.
#define ATTN_SMEM (32768 + 2 * 16384)

__device__ __forceinline__ void mma_chunk64(float (&acc)[2][8][4], uint32_t qb, uint32_t kb,
                                            int l, int w) {
    #pragma unroll
    for (int mt = 0; mt < 2; mt++)
        #pragma unroll
        for (int nt = 0; nt < 8; nt++)
            #pragma unroll
            for (int e = 0; e < 4; e++) acc[mt][nt][e] = 0.f;

    #pragma unroll
    for (int s = 0; s < 4; s++) {
        const int acol = s * 32 + ((l >> 4) << 4);
        uint32_t ah[2][4], al[2][4];
        #pragma unroll
        for (int mt = 0; mt < 2; mt++) {
            const int arow = 32 * w + mt * 16 + (l & 15);
            LDSM4(ah[mt], qb + SW128(arow * 128 + acol));
            LDSM4(al[mt], qb + 16384 + SW128(arow * 128 + acol));
        }
        #pragma unroll
        for (int tp = 0; tp < 4; tp++) {
            const int brow = tp * 16 + (l & 7) + ((l >> 4) << 3);
            const int bcol = s * 32 + (((l >> 3) & 1) << 4);
            uint32_t bhf[4], blf[4];
            LDSM4(bhf, kb + SW128(brow * 128 + bcol));
            LDSM4(blf, kb + 8192 + SW128(brow * 128 + bcol));
            #pragma unroll
            for (int mt = 0; mt < 2; mt++)
                #pragma unroll
                for (int nn = 0; nn < 2; nn++) {
                    float* c = acc[mt][2 * tp + nn];
                    mma_bf16(c, ah[mt], bhf + 2 * nn);
                    mma_bf16(c, ah[mt], blf + 2 * nn);
                    mma_bf16(c, al[mt], bhf + 2 * nn);
                }
        }
    }
}

__global__ __launch_bounds__(128, 3) void attn_fused(float* __restrict__ out) {
    extern __shared__ char smem[];
    const int tid = threadIdx.x, l = tid & 31, w = tid >> 5;
    const int bx = 15 - blockIdx.x;                // big tiles launch first
    const int t0 = bx * 128;
    const int bh = blockIdx.z * H_ + blockIdx.y;
    const uint32_t sb = smem_addr(smem);

    const __nv_bfloat16* qh = g_qh + ((size_t)bh * S_ + t0) * HD_;
    const __nv_bfloat16* ql = g_ql + ((size_t)bh * S_ + t0) * HD_;
    const __nv_bfloat16* khb = g_kh + (size_t)bh * S_ * HD_;
    const __nv_bfloat16* klb = g_kl + (size_t)bh * S_ * HD_;

    auto prefetch_k = [&](int buf, int chunk) {      // 64-row chunk: 16KB
        const __nv_bfloat16* kh = khb + (size_t)chunk * 64 * HD_;
        const __nv_bfloat16* kl = klb + (size_t)chunk * 64 * HD_;
        #pragma unroll
        for (int i = 0; i < 8; i++) {
            int gi = tid + i * 128;
            int tl = gi >> 9, idx = gi & 511, row = idx >> 3, c8 = idx & 7;
            CP_ASYNC16(sb + 32768 + buf * 16384 + tl * 8192 + SW128(row * 128 + c8 * 16),
                       (tl ? kl : kh) + row * HD_ + c8 * 8);
        }
    };

    const int nj = 2 * bx + 2;                     // causal 64-col chunks
    const int nfut = 32 - nj;                      // future (all-zero) 64-col chunks
    const int cbase = 64 * nj;
    const float4 z4 = make_float4(0.f, 0.f, 0.f, 0.f);
    auto zfill = [&](int c) {                      // zero one 64-col x 128-row chunk
        float4* p = (float4*)(out + ((size_t)bh * S_ + t0 + tid) * S_ + cbase + 64 * c);
        #pragma unroll
        for (int i = 0; i < 16; i++) __stcs(p + i, z4);
    };

    // Q (persistent, 32KB) + K chunk 0
    #pragma unroll
    for (int i = 0; i < 16; i++) {
        int gi = tid + i * 128;
        int tl = gi >> 10, idx = gi & 1023, row = idx >> 3, c8 = idx & 7;
        CP_ASYNC16(sb + tl * 16384 + SW128(row * 128 + c8 * 16),
                   (tl ? ql : qh) + row * HD_ + c8 * 8);
    }
    prefetch_k(0, 0);
    CP_COMMIT();

    const int rq = (l >> 2);                       // quad row within 8
    float d[2][2] = {{0.f, 0.f}, {0.f, 0.f}};      // [mt][rowhalf] sums of 2^score

    // ---- phase A: row sums ----
    for (int j = 0; j < nj; j++) {
        CP_WAIT0();
        __syncthreads();
        prefetch_k((j + 1) & 1, (j + 1 < nj) ? j + 1 : 0);   // wraps to phase-B chunk 0
        CP_COMMIT();

        const uint32_t kb = sb + 32768 + (j & 1) * 16384;
        float acc[2][8][4];
        mma_chunk64(acc, sb, kb, l, w);

        const bool diag = (j >= 2 * bx);
        const int coff = (j - 2 * bx) * 64;
        #pragma unroll
        for (int mt = 0; mt < 2; mt++) {
            const int rr0 = 32 * w + 16 * mt + rq, rr1 = rr0 + 8;
            #pragma unroll
            for (int nt = 0; nt < 8; nt++)
                #pragma unroll
                for (int e = 0; e < 2; e++) {
                    const int cl = nt * 8 + 2 * (l & 3) + e;
                    float e0 = ex2(acc[mt][nt][e]);
                    float e1 = ex2(acc[mt][nt][2 + e]);
                    if (diag) {
                        if (coff + cl > rr0) e0 = 0.f;
                        if (coff + cl > rr1) e1 = 0.f;
                    }
                    d[mt][0] += e0; d[mt][1] += e1;
                }
        }
        if (j < nfut) zfill(j);                    // overlapped zero-fill
    }

    // full row sum lives in the 4 lanes of each quad
    #pragma unroll
    for (int off = 1; off <= 2; off <<= 1) {
        #pragma unroll
        for (int mt = 0; mt < 2; mt++) {
            d[mt][0] += __shfl_xor_sync(0xffffffffu, d[mt][0], off);
            d[mt][1] += __shfl_xor_sync(0xffffffffu, d[mt][1], off);
        }
    }
    float vi[2][2];
    #pragma unroll
    for (int mt = 0; mt < 2; mt++) {
        vi[mt][0] = 1.f / d[mt][0];
        vi[mt][1] = 1.f / d[mt][1];
    }

    // ---- phase B: probabilities ----
    for (int j = 0; j < nj; j++) {
        CP_WAIT0();
        __syncthreads();
        if (j + 1 < nj) { prefetch_k((nj + j + 1) & 1, j + 1); CP_COMMIT(); }

        const uint32_t kb = sb + 32768 + ((nj + j) & 1) * 16384;
        float acc[2][8][4];
        mma_chunk64(acc, sb, kb, l, w);

        const bool diag = (j >= 2 * bx);
        const int coff = (j - 2 * bx) * 64;
        #pragma unroll
        for (int mt = 0; mt < 2; mt++) {
            const int rr0 = 32 * w + 16 * mt + rq, rr1 = rr0 + 8;
            float* o0 = out + ((size_t)bh * S_ + t0 + rr0) * S_ + j * 64 + 2 * (l & 3);
            float* o1 = out + ((size_t)bh * S_ + t0 + rr1) * S_ + j * 64 + 2 * (l & 3);
            #pragma unroll
            for (int nt = 0; nt < 8; nt++) {
                const int cl = nt * 8 + 2 * (l & 3);
                float2 p0, p1;
                p0.x = ex2(acc[mt][nt][0]) * vi[mt][0];
                p0.y = ex2(acc[mt][nt][1]) * vi[mt][0];
                p1.x = ex2(acc[mt][nt][2]) * vi[mt][1];
                p1.y = ex2(acc[mt][nt][3]) * vi[mt][1];
                if (diag) {
                    if (coff + cl     > rr0) p0.x = 0.f;
                    if (coff + cl + 1 > rr0) p0.y = 0.f;
                    if (coff + cl     > rr1) p1.x = 0.f;
                    if (coff + cl + 1 > rr1) p1.y = 0.f;
                }
                __stcs((float2*)(o0 + nt * 8), p0);
                __stcs((float2*)(o1 + nt * 8), p1);
            }
        }
        if (nj + j < nfut) zfill(nj + j);          // overlapped zero-fill (continued)
    }

    // leftover zero chunks (only for small-bx blocks, which finish early anyway)
    for (int c = 2 * nj; c < nfut; c++) zfill(c);
}

// ---------------------------------------------------------------------------
extern "C" void kernel_launch(void* const* d_in, const int* in_sizes, int n_in,
                              void* d_out, int out_size)
{
    (void)in_sizes; (void)n_in; (void)out_size;
    const float* encoded = (const float*)d_in[0];  // [2, 2048, 1024]
    const float* W       = (const float*)d_in[1];  // [2048, 1024]
    const float* bias    = (const float*)d_in[2];  // [2048]
    float* out = (float*)d_out;                    // [2, 16, 2048, 2048]

    cudaFuncSetAttribute(proj_mma,   cudaFuncAttributeMaxDynamicSharedMemorySize, PROJ_SMEM);
    cudaFuncSetAttribute(attn_fused, cudaFuncAttributeMaxDynamicSharedMemorySize, ATTN_SMEM);

    split_all<<<6144, 256>>>(encoded, W);
    proj_mma<<<dim3(32, 32), 128, PROJ_SMEM>>>(bias);
    attn_fused<<<dim3(16, H_, B_), 128, ATTN_SMEM>>>(out);
}

// round 12
// speedup vs baseline: 1.1623x; 1.0181x over previous
#include <cuda_runtime.h>
#include <cuda_bf16.h>
#include <cstdint>
#include <cstddef>

#define B_  2
#define S_  2048
#define D_  1024
#define H_  16
#define HD_ 64
#define LOG2E 1.4426950408889634f
#define SW128(o) ((o) ^ (((o) >> 3) & 0x70))
#define SW64(o)  ((o) ^ (((o) >> 3) & 0x30))

// ---------------- static device scratch (allocation-free rule) ----------------
__device__ __nv_bfloat16 g_enc_h[(size_t)4096 * 1024];
__device__ __nv_bfloat16 g_enc_l[(size_t)4096 * 1024];
__device__ __nv_bfloat16 g_w_h[(size_t)2048 * 1024];
__device__ __nv_bfloat16 g_w_l[(size_t)2048 * 1024];
__device__ __nv_bfloat16 g_qh[(size_t)B_ * H_ * S_ * HD_];
__device__ __nv_bfloat16 g_ql[(size_t)B_ * H_ * S_ * HD_];
__device__ __nv_bfloat16 g_kh[(size_t)B_ * H_ * S_ * HD_];
__device__ __nv_bfloat16 g_kl[(size_t)B_ * H_ * S_ * HD_];

// ---------------- helpers (family-common ISA only: sm_80+) ----------------
__device__ __forceinline__ uint32_t smem_addr(const void* p) {
    uint32_t a;
    asm("{ .reg .u64 t; cvta.to.shared.u64 t, %1; cvt.u32.u64 %0, t; }" : "=r"(a) : "l"(p));
    return a;
}
#define CP_ASYNC16(dst, src) \
    asm volatile("cp.async.cg.shared.global [%0], [%1], 16;" :: "r"(dst), "l"(src))
#define CP_COMMIT() asm volatile("cp.async.commit_group;" ::: "memory")
#define CP_WAIT0()  asm volatile("cp.async.wait_group 0;" ::: "memory")

#define LDSM4(r, a)                                                            \
    asm volatile("ldmatrix.sync.aligned.m8n8.x4.shared.b16 {%0,%1,%2,%3}, [%4];" \
        : "=r"((r)[0]), "=r"((r)[1]), "=r"((r)[2]), "=r"((r)[3]) : "r"(a))

__device__ __forceinline__ void mma_bf16(float* c, const uint32_t* a, const uint32_t* b) {
    asm volatile(
        "mma.sync.aligned.m16n8k16.row.col.f32.bf16.bf16.f32 "
        "{%0,%1,%2,%3}, {%4,%5,%6,%7}, {%8,%9}, {%0,%1,%2,%3};"
        : "+f"(c[0]), "+f"(c[1]), "+f"(c[2]), "+f"(c[3])
        : "r"(a[0]), "r"(a[1]), "r"(a[2]), "r"(a[3]), "r"(b[0]), "r"(b[1]));
}

__device__ __forceinline__ float ex2(float x) {
    float y;
    asm("ex2.approx.ftz.f32 %0, %1;" : "=f"(y) : "f"(x));
    return y;
}

__device__ __forceinline__ void split2(float a, float b, __nv_bfloat162& h, __nv_bfloat162& l) {
    __nv_bfloat16 ha = __float2bfloat16_rn(a), hb = __float2bfloat16_rn(b);
    h.x = ha; h.y = hb;
    l.x = __float2bfloat16_rn(a - __bfloat162float(ha));
    l.y = __float2bfloat16_rn(b - __bfloat162float(hb));
}

// ---------------- split kernel: fp32 -> bf16 hi/lo (enc + W in one launch) ----------------
__global__ void split_all(const float* __restrict__ enc, const float* __restrict__ Wm) {
    const int bx = blockIdx.x;
    if (bx < 4096) {
        int i = bx * 256 + threadIdx.x;
        float4 v = ((const float4*)enc)[i];
        __nv_bfloat162 h01, l01, h23, l23;
        split2(v.x, v.y, h01, l01);
        split2(v.z, v.w, h23, l23);
        ((__nv_bfloat162*)g_enc_h)[2 * i]     = h01;
        ((__nv_bfloat162*)g_enc_h)[2 * i + 1] = h23;
        ((__nv_bfloat162*)g_enc_l)[2 * i]     = l01;
        ((__nv_bfloat162*)g_enc_l)[2 * i + 1] = l23;
    } else {
        int i = (bx - 4096) * 256 + threadIdx.x;
        float4 v = ((const float4*)Wm)[i];
        __nv_bfloat162 h01, l01, h23, l23;
        split2(v.x, v.y, h01, l01);
        split2(v.z, v.w, h23, l23);
        ((__nv_bfloat162*)g_w_h)[2 * i]     = h01;
        ((__nv_bfloat162*)g_w_h)[2 * i + 1] = h23;
        ((__nv_bfloat162*)g_w_l)[2 * i]     = l01;
        ((__nv_bfloat162*)g_w_l)[2 * i + 1] = l23;
    }
}

// ---------------- projection GEMM: qk = enc @ W^T + bias ----------------
// Block tile 128(M) x 64(N), 4 warps x (32x64), K-chunk 32 (SW64, 64B rows).
// smem buf (24KB): Ah@0 Al@8192 Bh@16384 Bl@20480 ; x2 bufs = 48KB -> 4 blocks/SM
#define PROJ_BUF 24576
#define PROJ_SMEM (2 * PROJ_BUF)

__global__ __launch_bounds__(128, 4) void proj_mma(const float* __restrict__ bias) {
    extern __shared__ char smem[];
    const int tid = threadIdx.x, l = tid & 31, w = tid >> 5;
    const int e0 = blockIdx.x * 64, m0 = blockIdx.y * 128;
    const uint32_t sb = smem_addr(smem);

    auto prefetch = [&](int buf, int k0) {
        #pragma unroll
        for (int i = 0; i < 12; i++) {
            int gi = tid + i * 128;                 // 0..1535
            const __nv_bfloat16* src;
            uint32_t dst;
            if (gi < 1024) {                        // A: 128 rows x 4 c8 x (h,l)
                int tl = gi >> 9, idx = gi & 511, row = idx >> 2, c8 = idx & 3;
                src = (tl ? g_enc_l : g_enc_h) + (size_t)(m0 + row) * D_ + k0 + c8 * 8;
                dst = sb + buf * PROJ_BUF + tl * 8192 + SW64(row * 64 + c8 * 16);
            } else {                                // B: 64 rows x 4 c8 x (h,l)
                int gj = gi - 1024;
                int tl = gj >> 8, idx = gj & 255, row = idx >> 2, c8 = idx & 3;
                src = (tl ? g_w_l : g_w_h) + (size_t)(e0 + row) * D_ + k0 + c8 * 8;
                dst = sb + buf * PROJ_BUF + 16384 + tl * 4096 + SW64(row * 64 + c8 * 16);
            }
            CP_ASYNC16(dst, src);
        }
    };

    prefetch(0, 0);
    CP_COMMIT();

    float acc[2][8][4];
    #pragma unroll
    for (int mt = 0; mt < 2; mt++)
        #pragma unroll
        for (int nt = 0; nt < 8; nt++)
            #pragma unroll
            for (int e = 0; e < 4; e++) acc[mt][nt][e] = 0.f;

    for (int j = 0; j < 32; j++) {
        CP_WAIT0();
        __syncthreads();
        if (j < 31) { prefetch((j + 1) & 1, (j + 1) * 32); CP_COMMIT(); }

        const uint32_t tb = sb + (j & 1) * PROJ_BUF;
        #pragma unroll
        for (int s = 0; s < 2; s++) {
            const int acol = s * 32 + ((l >> 4) << 4);
            uint32_t ah[2][4], al[2][4];
            #pragma unroll
            for (int mt = 0; mt < 2; mt++) {
                const int arow = 32 * w + mt * 16 + (l & 15);
                LDSM4(ah[mt], tb + SW64(arow * 64 + acol));
                LDSM4(al[mt], tb + 8192 + SW64(arow * 64 + acol));
            }
            #pragma unroll
            for (int tp = 0; tp < 4; tp++) {
                const int brow = tp * 16 + (l & 7) + ((l >> 4) << 3);
                const int bcol = s * 32 + (((l >> 3) & 1) << 4);
                uint32_t bhf[4], blf[4];
                LDSM4(bhf, tb + 16384 + SW64(brow * 64 + bcol));
                LDSM4(blf, tb + 20480 + SW64(brow * 64 + bcol));
                #pragma unroll
                for (int mt = 0; mt < 2; mt++)
                    #pragma unroll
                    for (int nn = 0; nn < 2; nn++) {
                        float* c = acc[mt][2 * tp + nn];
                        mma_bf16(c, ah[mt], bhf + 2 * nn);
                        mma_bf16(c, ah[mt], blf + 2 * nn);
                        mma_bf16(c, al[mt], bhf + 2 * nn);
                    }
            }
        }
        // no bottom barrier: next iteration's top wait+sync fences buffer reuse
    }

    // Epilogue: bias; q gets 0.125*log2(e) folded in (scores land in log2 domain).
    const bool isq = (e0 < D_);
    const int eh = isq ? e0 : e0 - D_;
    const int head = eh >> 6;
    const float scf = isq ? (0.125f * LOG2E) : 1.0f;
    __nv_bfloat16* dhb = isq ? g_qh : g_kh;
    __nv_bfloat16* dlb = isq ? g_ql : g_kl;

    #pragma unroll
    for (int mt = 0; mt < 2; mt++)
        #pragma unroll
        for (int nt = 0; nt < 8; nt++) {
            const int cp = e0 + nt * 8 + 2 * (l & 3);
            const int hd0 = cp & 63;
            const float b0 = __ldg(bias + cp), b1 = __ldg(bias + cp + 1);
            #pragma unroll
            for (int rh = 0; rh < 2; rh++) {
                const int m = m0 + 32 * w + mt * 16 + (l >> 2) + rh * 8;
                const int bb = m >> 11, s = m & (S_ - 1);
                const size_t base = (((size_t)bb * H_ + head) * S_ + s) * HD_ + hd0;
                const float v0 = (acc[mt][nt][2 * rh]     + b0) * scf;
                const float v1 = (acc[mt][nt][2 * rh + 1] + b1) * scf;
                __nv_bfloat162 h2, l2;
                split2(v0, v1, h2, l2);
                *(__nv_bfloat162*)(dhb + base) = h2;
                *(__nv_bfloat162*)(dlb + base) = l2;
            }
        }
}

// ---------------- fused attention: 4 warps x 32 q-rows, 64-row K chunks (R9 config) ----------------
// smem: Q hi@0 lo@16384 ; K buf b at 32768 + b*16384 (hi@0 lo@8192 within buf)
// 64KB/block -> 3 blocks/SM; acc 64 regs -> no spills. Zero-fill as serial tail.
#define ATTN_SMEM (32768 + 2 * 16384)

__device__ __forceinline__ void mma_chunk64(float (&acc)[2][8][4], uint32_t qb, uint32_t kb,
                                            int l, int w) {
    #pragma unroll
    for (int mt = 0; mt < 2; mt++)
        #pragma unroll
        for (int nt = 0; nt < 8; nt++)
            #pragma unroll
            for (int e = 0; e < 4; e++) acc[mt][nt][e] = 0.f;

    #pragma unroll
    for (int s = 0; s < 4; s++) {
        const int acol = s * 32 + ((l >> 4) << 4);
        uint32_t ah[2][4], al[2][4];
        #pragma unroll
        for (int mt = 0; mt < 2; mt++) {
            const int arow = 32 * w + mt * 16 + (l & 15);
            LDSM4(ah[mt], qb + SW128(arow * 128 + acol));
            LDSM4(al[mt], qb + 16384 + SW128(arow * 128 + acol));
        }
        #pragma unroll
        for (int tp = 0; tp < 4; tp++) {
            const int brow = tp * 16 + (l & 7) + ((l >> 4) << 3);
            const int bcol = s * 32 + (((l >> 3) & 1) << 4);
            uint32_t bhf[4], blf[4];
            LDSM4(bhf, kb + SW128(brow * 128 + bcol));
            LDSM4(blf, kb + 8192 + SW128(brow * 128 + bcol));
            #pragma unroll
            for (int mt = 0; mt < 2; mt++)
                #pragma unroll
                for (int nn = 0; nn < 2; nn++) {
                    float* c = acc[mt][2 * tp + nn];
                    mma_bf16(c, ah[mt], bhf + 2 * nn);
                    mma_bf16(c, ah[mt], blf + 2 * nn);
                    mma_bf16(c, al[mt], bhf + 2 * nn);
                }
        }
    }
}

__global__ __launch_bounds__(128, 3) void attn_fused(float* __restrict__ out) {
    extern __shared__ char smem[];
    const int tid = threadIdx.x, l = tid & 31, w = tid >> 5;
    const int bx = 15 - blockIdx.x;                // big tiles launch first
    const int t0 = bx * 128;
    const int bh = blockIdx.z * H_ + blockIdx.y;
    const uint32_t sb = smem_addr(smem);

    const __nv_bfloat16* qh = g_qh + ((size_t)bh * S_ + t0) * HD_;
    const __nv_bfloat16* ql = g_ql + ((size_t)bh * S_ + t0) * HD_;
    const __nv_bfloat16* khb = g_kh + (size_t)bh * S_ * HD_;
    const __nv_bfloat16* klb = g_kl + (size_t)bh * S_ * HD_;

    auto prefetch_k = [&](int buf, int chunk) {      // 64-row chunk: 16KB
        const __nv_bfloat16* kh = khb + (size_t)chunk * 64 * HD_;
        const __nv_bfloat16* kl = klb + (size_t)chunk * 64 * HD_;
        #pragma unroll
        for (int i = 0; i < 8; i++) {
            int gi = tid + i * 128;
            int tl = gi >> 9, idx = gi & 511, row = idx >> 3, c8 = idx & 7;
            CP_ASYNC16(sb + 32768 + buf * 16384 + tl * 8192 + SW128(row * 128 + c8 * 16),
                       (tl ? kl : kh) + row * HD_ + c8 * 8);
        }
    };

    // Q (persistent, 32KB) + K chunk 0
    #pragma unroll
    for (int i = 0; i < 16; i++) {
        int gi = tid + i * 128;
        int tl = gi >> 10, idx = gi & 1023, row = idx >> 3, c8 = idx & 7;
        CP_ASYNC16(sb + tl * 16384 + SW128(row * 128 + c8 * 16),
                   (tl ? ql : qh) + row * HD_ + c8 * 8);
    }
    prefetch_k(0, 0);
    CP_COMMIT();

    const int rq = (l >> 2);                       // quad row within 8
    const int nj = 2 * bx + 2;                     // causal 64-col chunks
    float d[2][2] = {{0.f, 0.f}, {0.f, 0.f}};      // [mt][rowhalf] sums of 2^score

    // ---- phase A: row sums ----
    for (int j = 0; j < nj; j++) {
        CP_WAIT0();
        __syncthreads();
        prefetch_k((j + 1) & 1, (j + 1 < nj) ? j + 1 : 0);   // wraps to phase-B chunk 0
        CP_COMMIT();

        const uint32_t kb = sb + 32768 + (j & 1) * 16384;
        float acc[2][8][4];
        mma_chunk64(acc, sb, kb, l, w);

        const bool diag = (j >= 2 * bx);
        const int coff = (j - 2 * bx) * 64;
        #pragma unroll
        for (int mt = 0; mt < 2; mt++) {
            const int rr0 = 32 * w + 16 * mt + rq, rr1 = rr0 + 8;
            #pragma unroll
            for (int nt = 0; nt < 8; nt++)
                #pragma unroll
                for (int e = 0; e < 2; e++) {
                    const int cl = nt * 8 + 2 * (l & 3) + e;
                    float e0 = ex2(acc[mt][nt][e]);
                    float e1 = ex2(acc[mt][nt][2 + e]);
                    if (diag) {
                        if (coff + cl > rr0) e0 = 0.f;
                        if (coff + cl > rr1) e1 = 0.f;
                    }
                    d[mt][0] += e0; d[mt][1] += e1;
                }
        }
    }

    // full row sum lives in the 4 lanes of each quad
    #pragma unroll
    for (int off = 1; off <= 2; off <<= 1) {
        #pragma unroll
        for (int mt = 0; mt < 2; mt++) {
            d[mt][0] += __shfl_xor_sync(0xffffffffu, d[mt][0], off);
            d[mt][1] += __shfl_xor_sync(0xffffffffu, d[mt][1], off);
        }
    }
    float vi[2][2];
    #pragma unroll
    for (int mt = 0; mt < 2; mt++) {
        vi[mt][0] = 1.f / d[mt][0];
        vi[mt][1] = 1.f / d[mt][1];
    }

    // ---- phase B: probabilities ----
    for (int j = 0; j < nj; j++) {
        CP_WAIT0();
        __syncthreads();
        if (j + 1 < nj) { prefetch_k((nj + j + 1) & 1, j + 1); CP_COMMIT(); }

        const uint32_t kb = sb + 32768 + ((nj + j) & 1) * 16384;
        float acc[2][8][4];
        mma_chunk64(acc, sb, kb, l, w);

        const bool diag = (j >= 2 * bx);
        const int coff = (j - 2 * bx) * 64;
        #pragma unroll
        for (int mt = 0; mt < 2; mt++) {
            const int rr0 = 32 * w + 16 * mt + rq, rr1 = rr0 + 8;
            float* o0 = out + ((size_t)bh * S_ + t0 + rr0) * S_ + j * 64 + 2 * (l & 3);
            float* o1 = out + ((size_t)bh * S_ + t0 + rr1) * S_ + j * 64 + 2 * (l & 3);
            #pragma unroll
            for (int nt = 0; nt < 8; nt++) {
                const int cl = nt * 8 + 2 * (l & 3);
                float2 p0, p1;
                p0.x = ex2(acc[mt][nt][0]) * vi[mt][0];
                p0.y = ex2(acc[mt][nt][1]) * vi[mt][0];
                p1.x = ex2(acc[mt][nt][2]) * vi[mt][1];
                p1.y = ex2(acc[mt][nt][3]) * vi[mt][1];
                if (diag) {
                    if (coff + cl     > rr0) p0.x = 0.f;
                    if (coff + cl + 1 > rr0) p0.y = 0.f;
                    if (coff + cl     > rr1) p1.x = 0.f;
                    if (coff + cl + 1 > rr1) p1.y = 0.f;
                }
                __stcs((float2*)(o0 + nt * 8), p0);
                __stcs((float2*)(o1 + nt * 8), p1);
            }
        }
    }

    // zero-fill strictly-future columns (serial tail; one row per thread)
    const int cbase = 64 * nj;                     // == 128*(bx+1)
    const int len = S_ - cbase;
    if (len > 0) {
        float4* p = (float4*)(out + ((size_t)bh * S_ + t0 + tid) * S_ + cbase);
        const int n4 = len >> 2;
        const float4 z = make_float4(0.f, 0.f, 0.f, 0.f);
        for (int i = 0; i < n4; i++) __stcs(p + i, z);
    }
}

// ---------------------------------------------------------------------------
extern "C" void kernel_launch(void* const* d_in, const int* in_sizes, int n_in,
                              void* d_out, int out_size)
{
    (void)in_sizes; (void)n_in; (void)out_size;
    const float* encoded = (const float*)d_in[0];  // [2, 2048, 1024]
    const float* W       = (const float*)d_in[1];  // [2048, 1024]
    const float* bias    = (const float*)d_in[2];  // [2048]
    float* out = (float*)d_out;                    // [2, 16, 2048, 2048]

    cudaFuncSetAttribute(proj_mma,   cudaFuncAttributeMaxDynamicSharedMemorySize, PROJ_SMEM);
    cudaFuncSetAttribute(attn_fused, cudaFuncAttributeMaxDynamicSharedMemorySize, ATTN_SMEM);

    split_all<<<6144, 256>>>(encoded, W);
    proj_mma<<<dim3(32, 32), 128, PROJ_SMEM>>>(bias);
    attn_fused<<<dim3(16, H_, B_), 128, ATTN_SMEM>>>(out);
}

// round 13
// speedup vs baseline: 1.1907x; 1.0244x over previous
#include <cuda_runtime.h>
#include <cuda_bf16.h>
#include <cstdint>
#include <cstddef>

#define B_  2
#define S_  2048
#define D_  1024
#define H_  16
#define HD_ 64
#define LOG2E 1.4426950408889634f
#define SW128(o) ((o) ^ (((o) >> 3) & 0x70))

// ---------------- static device scratch (allocation-free rule) ----------------
__device__ __nv_bfloat16 g_enc_h[(size_t)4096 * 1024];
__device__ __nv_bfloat16 g_enc_l[(size_t)4096 * 1024];
__device__ __nv_bfloat16 g_w_h[(size_t)2048 * 1024];
__device__ __nv_bfloat16 g_w_l[(size_t)2048 * 1024];
__device__ __nv_bfloat16 g_qh[(size_t)B_ * H_ * S_ * HD_];
__device__ __nv_bfloat16 g_ql[(size_t)B_ * H_ * S_ * HD_];
__device__ __nv_bfloat16 g_kh[(size_t)B_ * H_ * S_ * HD_];
__device__ __nv_bfloat16 g_kl[(size_t)B_ * H_ * S_ * HD_];

// ---------------- helpers (family-common ISA only: sm_80+) ----------------
__device__ __forceinline__ uint32_t smem_addr(const void* p) {
    uint32_t a;
    asm("{ .reg .u64 t; cvta.to.shared.u64 t, %1; cvt.u32.u64 %0, t; }" : "=r"(a) : "l"(p));
    return a;
}
#define CP_ASYNC16(dst, src) \
    asm volatile("cp.async.cg.shared.global [%0], [%1], 16;" :: "r"(dst), "l"(src))
#define CP_COMMIT() asm volatile("cp.async.commit_group;" ::: "memory")
#define CP_WAIT0()  asm volatile("cp.async.wait_group 0;" ::: "memory")

#define LDSM4(r, a)                                                            \
    asm volatile("ldmatrix.sync.aligned.m8n8.x4.shared.b16 {%0,%1,%2,%3}, [%4];" \
        : "=r"((r)[0]), "=r"((r)[1]), "=r"((r)[2]), "=r"((r)[3]) : "r"(a))

__device__ __forceinline__ void mma_bf16(float* c, const uint32_t* a, const uint32_t* b) {
    asm volatile(
        "mma.sync.aligned.m16n8k16.row.col.f32.bf16.bf16.f32 "
        "{%0,%1,%2,%3}, {%4,%5,%6,%7}, {%8,%9}, {%0,%1,%2,%3};"
        : "+f"(c[0]), "+f"(c[1]), "+f"(c[2]), "+f"(c[3])
        : "r"(a[0]), "r"(a[1]), "r"(a[2]), "r"(a[3]), "r"(b[0]), "r"(b[1]));
}

__device__ __forceinline__ float ex2(float x) {
    float y;
    asm("ex2.approx.ftz.f32 %0, %1;" : "=f"(y) : "f"(x));
    return y;
}

__device__ __forceinline__ void split2(float a, float b, __nv_bfloat162& h, __nv_bfloat162& l) {
    __nv_bfloat16 ha = __float2bfloat16_rn(a), hb = __float2bfloat16_rn(b);
    h.x = ha; h.y = hb;
    l.x = __float2bfloat16_rn(a - __bfloat162float(ha));
    l.y = __float2bfloat16_rn(b - __bfloat162float(hb));
}

// ---------------- split kernel: fp32 -> bf16 hi/lo (enc + W in one launch) ----------------
__global__ void split_all(const float* __restrict__ enc, const float* __restrict__ Wm) {
    const int bx = blockIdx.x;
    if (bx < 4096) {
        int i = bx * 256 + threadIdx.x;
        float4 v = ((const float4*)enc)[i];
        __nv_bfloat162 h01, l01, h23, l23;
        split2(v.x, v.y, h01, l01);
        split2(v.z, v.w, h23, l23);
        ((__nv_bfloat162*)g_enc_h)[2 * i]     = h01;
        ((__nv_bfloat162*)g_enc_h)[2 * i + 1] = h23;
        ((__nv_bfloat162*)g_enc_l)[2 * i]     = l01;
        ((__nv_bfloat162*)g_enc_l)[2 * i + 1] = l23;
    } else {
        int i = (bx - 4096) * 256 + threadIdx.x;
        float4 v = ((const float4*)Wm)[i];
        __nv_bfloat162 h01, l01, h23, l23;
        split2(v.x, v.y, h01, l01);
        split2(v.z, v.w, h23, l23);
        ((__nv_bfloat162*)g_w_h)[2 * i]     = h01;
        ((__nv_bfloat162*)g_w_h)[2 * i + 1] = h23;
        ((__nv_bfloat162*)g_w_l)[2 * i]     = l01;
        ((__nv_bfloat162*)g_w_l)[2 * i + 1] = l23;
    }
}

// ---------------- projection GEMM: qk = enc @ W^T + bias (R9 config) ----------------
// Block tile 128(M) x 64(N), 4 warps x (32x64), K-chunk 64.
// smem buf (48KB): Ah@0 Al@16384 Bh@32768 Bl@40960 ; x2 buffers = 96KB -> 2 blocks/SM
#define PROJ_BUF 49152
#define PROJ_SMEM (2 * PROJ_BUF)

__global__ __launch_bounds__(128, 2) void proj_mma(const float* __restrict__ bias) {
    extern __shared__ char smem[];
    const int tid = threadIdx.x, l = tid & 31, w = tid >> 5;
    const int e0 = blockIdx.x * 64, m0 = blockIdx.y * 128;
    const uint32_t sb = smem_addr(smem);

    auto prefetch = [&](int buf, int k0) {
        #pragma unroll
        for (int i = 0; i < 24; i++) {
            int gi = tid + i * 128;                 // 0..3071
            const __nv_bfloat16* src;
            uint32_t dst;
            if (gi < 2048) {                        // A: 128 rows x 8 c8 x (h,l)
                int tl = gi >> 10, idx = gi & 1023, row = idx >> 3, c8 = idx & 7;
                src = (tl ? g_enc_l : g_enc_h) + (size_t)(m0 + row) * D_ + k0 + c8 * 8;
                dst = sb + buf * PROJ_BUF + tl * 16384 + SW128(row * 128 + c8 * 16);
            } else {                                // B: 64 rows x 8 c8 x (h,l)
                int gj = gi - 2048;
                int tl = gj >> 9, idx = gj & 511, row = idx >> 3, c8 = idx & 7;
                src = (tl ? g_w_l : g_w_h) + (size_t)(e0 + row) * D_ + k0 + c8 * 8;
                dst = sb + buf * PROJ_BUF + 32768 + tl * 8192 + SW128(row * 128 + c8 * 16);
            }
            CP_ASYNC16(dst, src);
        }
    };

    prefetch(0, 0);
    CP_COMMIT();

    float acc[2][8][4];
    #pragma unroll
    for (int mt = 0; mt < 2; mt++)
        #pragma unroll
        for (int nt = 0; nt < 8; nt++)
            #pragma unroll
            for (int e = 0; e < 4; e++) acc[mt][nt][e] = 0.f;

    for (int j = 0; j < 16; j++) {
        CP_WAIT0();
        __syncthreads();
        if (j < 15) { prefetch((j + 1) & 1, (j + 1) * 64); CP_COMMIT(); }

        const uint32_t tb = sb + (j & 1) * PROJ_BUF;
        #pragma unroll
        for (int s = 0; s < 4; s++) {
            const int acol = s * 32 + ((l >> 4) << 4);
            uint32_t ah[2][4], al[2][4];
            #pragma unroll
            for (int mt = 0; mt < 2; mt++) {
                const int arow = 32 * w + mt * 16 + (l & 15);
                LDSM4(ah[mt], tb + SW128(arow * 128 + acol));
                LDSM4(al[mt], tb + 16384 + SW128(arow * 128 + acol));
            }
            #pragma unroll
            for (int tp = 0; tp < 4; tp++) {
                const int brow = tp * 16 + (l & 7) + ((l >> 4) << 3);
                const int bcol = s * 32 + (((l >> 3) & 1) << 4);
                uint32_t bhf[4], blf[4];
                LDSM4(bhf, tb + 32768 + SW128(brow * 128 + bcol));
                LDSM4(blf, tb + 40960 + SW128(brow * 128 + bcol));
                #pragma unroll
                for (int mt = 0; mt < 2; mt++)
                    #pragma unroll
                    for (int nn = 0; nn < 2; nn++) {
                        float* c = acc[mt][2 * tp + nn];
                        mma_bf16(c, ah[mt], bhf + 2 * nn);
                        mma_bf16(c, ah[mt], blf + 2 * nn);
                        mma_bf16(c, al[mt], bhf + 2 * nn);
                    }
            }
        }
        __syncthreads();
    }

    // Epilogue: bias; q gets 0.125*log2(e) folded in (scores land in log2 domain).
    const bool isq = (e0 < D_);
    const int eh = isq ? e0 : e0 - D_;
    const int head = eh >> 6;
    const float scf = isq ? (0.125f * LOG2E) : 1.0f;
    __nv_bfloat16* dhb = isq ? g_qh : g_kh;
    __nv_bfloat16* dlb = isq ? g_ql : g_kl;

    #pragma unroll
    for (int mt = 0; mt < 2; mt++)
        #pragma unroll
        for (int nt = 0; nt < 8; nt++) {
            const int cp = e0 + nt * 8 + 2 * (l & 3);
            const int hd0 = cp & 63;
            const float b0 = __ldg(bias + cp), b1 = __ldg(bias + cp + 1);
            #pragma unroll
            for (int rh = 0; rh < 2; rh++) {
                const int m = m0 + 32 * w + mt * 16 + (l >> 2) + rh * 8;
                const int bb = m >> 11, s = m & (S_ - 1);
                const size_t base = (((size_t)bb * H_ + head) * S_ + s) * HD_ + hd0;
                const float v0 = (acc[mt][nt][2 * rh]     + b0) * scf;
                const float v1 = (acc[mt][nt][2 * rh + 1] + b1) * scf;
                __nv_bfloat162 h2, l2;
                split2(v0, v1, h2, l2);
                *(__nv_bfloat162*)(dhb + base) = h2;
                *(__nv_bfloat162*)(dlb + base) = l2;
            }
        }
}

// ---------------- fused attention: Q fragments hoisted to registers ----------------
// smem (32KB total): initially Q hi@0 lo@16384 (staging for ldmatrix hoist);
// after the hoist the SAME region becomes 2 K buffers: buf b at b*16384
// (hi@+0, lo@+8192). Occupancy: regs-limited, 3 blocks/SM (128 thr x ~170 regs).
#define ATTN_SMEM 32768

__device__ __forceinline__ void mma_chunk64_qr(float (&acc)[2][8][4],
                                               const uint32_t (&qfh)[4][2][4],
                                               const uint32_t (&qfl)[4][2][4],
                                               uint32_t kb, int l) {
    #pragma unroll
    for (int mt = 0; mt < 2; mt++)
        #pragma unroll
        for (int nt = 0; nt < 8; nt++)
            #pragma unroll
            for (int e = 0; e < 4; e++) acc[mt][nt][e] = 0.f;

    #pragma unroll
    for (int s = 0; s < 4; s++) {
        #pragma unroll
        for (int tp = 0; tp < 4; tp++) {
            const int brow = tp * 16 + (l & 7) + ((l >> 4) << 3);
            const int bcol = s * 32 + (((l >> 3) & 1) << 4);
            uint32_t bhf[4], blf[4];
            LDSM4(bhf, kb + SW128(brow * 128 + bcol));
            LDSM4(blf, kb + 8192 + SW128(brow * 128 + bcol));
            #pragma unroll
            for (int mt = 0; mt < 2; mt++)
                #pragma unroll
                for (int nn = 0; nn < 2; nn++) {
                    float* c = acc[mt][2 * tp + nn];
                    mma_bf16(c, qfh[s][mt], bhf + 2 * nn);
                    mma_bf16(c, qfh[s][mt], blf + 2 * nn);
                    mma_bf16(c, qfl[s][mt], bhf + 2 * nn);
                }
        }
    }
}

__global__ __launch_bounds__(128, 3) void attn_fused(float* __restrict__ out) {
    extern __shared__ char smem[];
    const int tid = threadIdx.x, l = tid & 31, w = tid >> 5;
    const int bx = 15 - blockIdx.x;                // big tiles launch first
    const int t0 = bx * 128;
    const int bh = blockIdx.z * H_ + blockIdx.y;
    const uint32_t sb = smem_addr(smem);

    const __nv_bfloat16* qh = g_qh + ((size_t)bh * S_ + t0) * HD_;
    const __nv_bfloat16* ql = g_ql + ((size_t)bh * S_ + t0) * HD_;
    const __nv_bfloat16* khb = g_kh + (size_t)bh * S_ * HD_;
    const __nv_bfloat16* klb = g_kl + (size_t)bh * S_ * HD_;

    auto prefetch_k = [&](int buf, int chunk) {      // 64-row chunk: 16KB
        const __nv_bfloat16* kh = khb + (size_t)chunk * 64 * HD_;
        const __nv_bfloat16* kl = klb + (size_t)chunk * 64 * HD_;
        #pragma unroll
        for (int i = 0; i < 8; i++) {
            int gi = tid + i * 128;
            int tl = gi >> 9, idx = gi & 511, row = idx >> 3, c8 = idx & 7;
            CP_ASYNC16(sb + buf * 16384 + tl * 8192 + SW128(row * 128 + c8 * 16),
                       (tl ? kl : kh) + row * HD_ + c8 * 8);
        }
    };

    // ---- Q staging + register hoist (smem reused for K afterwards) ----
    #pragma unroll
    for (int i = 0; i < 16; i++) {
        int gi = tid + i * 128;
        int tl = gi >> 10, idx = gi & 1023, row = idx >> 3, c8 = idx & 7;
        CP_ASYNC16(sb + tl * 16384 + SW128(row * 128 + c8 * 16),
                   (tl ? ql : qh) + row * HD_ + c8 * 8);
    }
    CP_COMMIT();
    CP_WAIT0();
    __syncthreads();

    uint32_t qfh[4][2][4], qfl[4][2][4];
    #pragma unroll
    for (int s = 0; s < 4; s++) {
        const int acol = s * 32 + ((l >> 4) << 4);
        #pragma unroll
        for (int mt = 0; mt < 2; mt++) {
            const int arow = 32 * w + mt * 16 + (l & 15);
            LDSM4(qfh[s][mt], sb + SW128(arow * 128 + acol));
            LDSM4(qfl[s][mt], sb + 16384 + SW128(arow * 128 + acol));
        }
    }
    __syncthreads();                               // Q reads done; smem now K's

    prefetch_k(0, 0);
    CP_COMMIT();

    const int rq = (l >> 2);                       // quad row within 8
    const int nj = 2 * bx + 2;                     // causal 64-col chunks
    float d[2][2] = {{0.f, 0.f}, {0.f, 0.f}};      // [mt][rowhalf] sums of 2^score

    // ---- phase A: row sums ----
    for (int j = 0; j < nj; j++) {
        CP_WAIT0();
        __syncthreads();
        prefetch_k((j + 1) & 1, (j + 1 < nj) ? j + 1 : 0);   // wraps to phase-B chunk 0
        CP_COMMIT();

        const uint32_t kb = sb + (j & 1) * 16384;
        float acc[2][8][4];
        mma_chunk64_qr(acc, qfh, qfl, kb, l);

        const bool diag = (j >= 2 * bx);
        const int coff = (j - 2 * bx) * 64;
        #pragma unroll
        for (int mt = 0; mt < 2; mt++) {
            const int rr0 = 32 * w + 16 * mt + rq, rr1 = rr0 + 8;
            #pragma unroll
            for (int nt = 0; nt < 8; nt++)
                #pragma unroll
                for (int e = 0; e < 2; e++) {
                    const int cl = nt * 8 + 2 * (l & 3) + e;
                    float e0 = ex2(acc[mt][nt][e]);
                    float e1 = ex2(acc[mt][nt][2 + e]);
                    if (diag) {
                        if (coff + cl > rr0) e0 = 0.f;
                        if (coff + cl > rr1) e1 = 0.f;
                    }
                    d[mt][0] += e0; d[mt][1] += e1;
                }
        }
    }

    // full row sum lives in the 4 lanes of each quad
    #pragma unroll
    for (int off = 1; off <= 2; off <<= 1) {
        #pragma unroll
        for (int mt = 0; mt < 2; mt++) {
            d[mt][0] += __shfl_xor_sync(0xffffffffu, d[mt][0], off);
            d[mt][1] += __shfl_xor_sync(0xffffffffu, d[mt][1], off);
        }
    }
    float vi[2][2];
    #pragma unroll
    for (int mt = 0; mt < 2; mt++) {
        vi[mt][0] = 1.f / d[mt][0];
        vi[mt][1] = 1.f / d[mt][1];
    }

    // ---- phase B: probabilities ----
    for (int j = 0; j < nj; j++) {
        CP_WAIT0();
        __syncthreads();
        if (j + 1 < nj) { prefetch_k((nj + j + 1) & 1, j + 1); CP_COMMIT(); }

        const uint32_t kb = sb + ((nj + j) & 1) * 16384;
        float acc[2][8][4];
        mma_chunk64_qr(acc, qfh, qfl, kb, l);

        const bool diag = (j >= 2 * bx);
        const int coff = (j - 2 * bx) * 64;
        #pragma unroll
        for (int mt = 0; mt < 2; mt++) {
            const int rr0 = 32 * w + 16 * mt + rq, rr1 = rr0 + 8;
            float* o0 = out + ((size_t)bh * S_ + t0 + rr0) * S_ + j * 64 + 2 * (l & 3);
            float* o1 = out + ((size_t)bh * S_ + t0 + rr1) * S_ + j * 64 + 2 * (l & 3);
            #pragma unroll
            for (int nt = 0; nt < 8; nt++) {
                const int cl = nt * 8 + 2 * (l & 3);
                float2 p0, p1;
                p0.x = ex2(acc[mt][nt][0]) * vi[mt][0];
                p0.y = ex2(acc[mt][nt][1]) * vi[mt][0];
                p1.x = ex2(acc[mt][nt][2]) * vi[mt][1];
                p1.y = ex2(acc[mt][nt][3]) * vi[mt][1];
                if (diag) {
                    if (coff + cl     > rr0) p0.x = 0.f;
                    if (coff + cl + 1 > rr0) p0.y = 0.f;
                    if (coff + cl     > rr1) p1.x = 0.f;
                    if (coff + cl + 1 > rr1) p1.y = 0.f;
                }
                __stcs((float2*)(o0 + nt * 8), p0);
                __stcs((float2*)(o1 + nt * 8), p1);
            }
        }
    }

    // zero-fill strictly-future columns (serial tail; one row per thread)
    const int cbase = 64 * nj;                     // == 128*(bx+1)
    const int len = S_ - cbase;
    if (len > 0) {
        float4* p = (float4*)(out + ((size_t)bh * S_ + t0 + tid) * S_ + cbase);
        const int n4 = len >> 2;
        const float4 z = make_float4(0.f, 0.f, 0.f, 0.f);
        for (int i = 0; i < n4; i++) __stcs(p + i, z);
    }
}

// ---------------------------------------------------------------------------
extern "C" void kernel_launch(void* const* d_in, const int* in_sizes, int n_in,
                              void* d_out, int out_size)
{
    (void)in_sizes; (void)n_in; (void)out_size;
    const float* encoded = (const float*)d_in[0];  // [2, 2048, 1024]
    const float* W       = (const float*)d_in[1];  // [2048, 1024]
    const float* bias    = (const float*)d_in[2];  // [2048]
    float* out = (float*)d_out;                    // [2, 16, 2048, 2048]

    cudaFuncSetAttribute(proj_mma,   cudaFuncAttributeMaxDynamicSharedMemorySize, PROJ_SMEM);
    cudaFuncSetAttribute(attn_fused, cudaFuncAttributeMaxDynamicSharedMemorySize, ATTN_SMEM);

    split_all<<<6144, 256>>>(encoded, W);
    proj_mma<<<dim3(32, 32), 128, PROJ_SMEM>>>(bias);
    attn_fused<<<dim3(16, H_, B_), 128, ATTN_SMEM>>>(out);
}